// round 15
// baseline (speedup 1.0000x reference)
#include <cuda_runtime.h>
#include <cuda_fp16.h>
#include <cstdint>

#define NN 50000
#define NR 32
#define DD 64
#define NE_MAX 1600000
#define TILE 128
#define PADMAX (NR * TILE)
#define SAH 40    // As stride (u32): fp16 kpair LDS.64 frags conflict-free (8g+2tg)
#define SWH 72    // Wh stride (u32): scalar B LDS conflict-free (8tg+g)
#define WH_ROW 2048   // dense global W image per relation (32 kp x 64 n, u32)
#define ESTR 72   // epilogue stride

// Packed relation-sorted edges: (src, dst, norm_bits, 0)
__device__ int4     g_edge[NE_MAX + PADMAX];
__device__ int      g_binCount[NR];
__device__ int      g_cursor[NR];
__device__ int      g_tileRel[NE_MAX / TILE + NR + 2];
__device__ int      g_numTiles;
// Precomputed fp16 operands (rounded once, fragment-ready layouts)
__device__ uint32_t g_hH[(size_t)NN * 32];
__device__ uint32_t g_WH[(size_t)NR * WH_ROW];

__device__ __forceinline__ uint32_t packh2(float lo, float hi) {
    __half2 h2 = __floats2half2_rn(lo, hi);
    return *(uint32_t*)&h2;
}
__device__ __forceinline__ void mma_f16(float* c, const uint32_t* a,
                                        uint32_t b0, uint32_t b1) {
    asm volatile(
        "mma.sync.aligned.m16n8k16.row.col.f32.f16.f16.f32 "
        "{%0,%1,%2,%3}, {%4,%5,%6,%7}, {%8,%9}, {%0,%1,%2,%3};"
        : "+f"(c[0]), "+f"(c[1]), "+f"(c[2]), "+f"(c[3])
        : "r"(a[0]), "r"(a[1]), "r"(a[2]), "r"(a[3]), "r"(b0), "r"(b1));
}
__device__ __forceinline__ uint32_t smem_u32(const void* p) {
    uint32_t a;
    asm("{ .reg .u64 t; cvta.to.shared.u64 t, %1; cvt.u32.u64 %0, t; }" : "=r"(a) : "l"(p));
    return a;
}
__device__ __forceinline__ void cp16(uint32_t saddr, const void* gaddr) {
    asm volatile("cp.async.ca.shared.global [%0], [%1], 16;"
                 :: "r"(saddr), "l"(gaddr) : "memory");
}
#define CP_COMMIT() asm volatile("cp.async.commit_group;" ::: "memory")
#define CP_WAIT0()  asm volatile("cp.async.wait_group 0;" ::: "memory")

// ---------------------------------------------------------------------------
// Preamble A: fp16 fragment-layout conversion + relation histogram.
// ---------------------------------------------------------------------------
__global__ void __launch_bounds__(256) k_convert_hist(const float* __restrict__ h,
                                                      const float* __restrict__ W,
                                                      const int* __restrict__ rel,
                                                      int n_edges) {
    __shared__ int sh[NR];
    if (threadIdx.x < NR) sh[threadIdx.x] = 0;
    __syncthreads();

    const int i = blockIdx.x * 256 + threadIdx.x;
    if (i < NN * 32) {
        const int n = i >> 5, kp = i & 31;
        const int slot = (kp >> 3) * 8 + (kp & 3) * 2 + ((kp >> 2) & 1);
        g_hH[(n << 5) + slot] = packh2(__ldg(h + n * DD + 2 * kp),
                                       __ldg(h + n * DD + 2 * kp + 1));
    }
    if (i < NR * 32 * DD) {
        const int r = i >> 11, kp = (i >> 6) & 31, n = i & 63;
        const float* wp = W + (size_t)r * DD * DD + 2 * kp * DD + n;
        g_WH[(size_t)r * WH_ROW + (kp << 6) + n] = packh2(__ldg(wp), __ldg(wp + DD));
    }
    if (i < n_edges) atomicAdd(&sh[__ldg(rel + i)], 1);
    __syncthreads();
    if (threadIdx.x < NR && sh[threadIdx.x] > 0)
        atomicAdd(&g_binCount[threadIdx.x], sh[threadIdx.x]);
}

// ---------------------------------------------------------------------------
// Preamble B: TILE-aligned prefix, tile->rel map, pad zeroing. 32 threads.
// ---------------------------------------------------------------------------
__global__ void k_prefix() {
    int r = threadIdx.x;
    int cnt = g_binCount[r];
    int tiles = (cnt + TILE - 1) / TILE;
    int t = tiles;
#pragma unroll
    for (int d = 1; d < 32; d <<= 1) {
        int v = __shfl_up_sync(0xFFFFFFFFu, t, d);
        if (r >= d) t += v;
    }
    int tileBase = t - tiles;
    int base = tileBase * TILE;
    g_cursor[r] = base;
    for (int i = 0; i < tiles; i++) g_tileRel[tileBase + i] = r;
    for (int i = base + cnt; i < base + tiles * TILE; i++)
        g_edge[i] = make_int4(0, 0, 0, 0);
    if (r == 31) g_numTiles = t;
}

// ---------------------------------------------------------------------------
// Preamble C: scatter, 2 edges per thread.
// ---------------------------------------------------------------------------
__global__ void __launch_bounds__(256) k_scatter(const int* __restrict__ src,
                                                 const int* __restrict__ dst,
                                                 const int* __restrict__ rel,
                                                 const float* __restrict__ norm,
                                                 int n) {
    __shared__ int sh_cnt[NR], sh_base[NR];
    const int tid = threadIdx.x;
    if (tid < NR) sh_cnt[tid] = 0;
    __syncthreads();

    const int i0 = blockIdx.x * 512 + tid;
    const int i1 = i0 + 256;
    const bool ok0 = i0 < n, ok1 = i1 < n;
    int r0 = 0, r1 = 0, rank0 = 0, rank1 = 0;
    int4 e0, e1;
    if (ok0) {
        r0 = __ldg(rel + i0);
        e0 = make_int4(__ldg(src + i0), __ldg(dst + i0),
                       __float_as_int(__ldg(norm + i0)), 0);
        rank0 = atomicAdd(&sh_cnt[r0], 1);
    }
    if (ok1) {
        r1 = __ldg(rel + i1);
        e1 = make_int4(__ldg(src + i1), __ldg(dst + i1),
                       __float_as_int(__ldg(norm + i1)), 0);
        rank1 = atomicAdd(&sh_cnt[r1], 1);
    }
    __syncthreads();
    if (tid < NR && sh_cnt[tid] > 0)
        sh_base[tid] = atomicAdd(&g_cursor[tid], sh_cnt[tid]);
    __syncthreads();
    if (ok0) g_edge[sh_base[r0] + rank0] = e0;
    if (ok1) g_edge[sh_base[r1] + rank1] = e1;
}

// ---------------------------------------------------------------------------
// Fused kernel: one 128-edge tile per block, fp16 mma m16n8k16.
// Smem 37.9 KB; __launch_bounds__(128, 6): <=85 regs -> 6 blocks/SM (227 KB).
// B fragments loaded per-nt (2 live regs) to fit the register budget.
// ---------------------------------------------------------------------------
__global__ void __launch_bounds__(128, 6) rgcn_fused(float* __restrict__ out) {
    extern __shared__ uint32_t smem[];
    uint32_t* Wh     = smem;                  // 2304
    uint32_t* As     = smem + 32 * SWH;       // 5120
    float*    E      = (float*)smem;          // epilogue overlay 128x72
    int*      s_dst  = (int*)(smem + 9216);   // 128
    float*    s_norm = (float*)(s_dst + 128); // 128

    const int tile = blockIdx.x;
    if (tile >= g_numTiles) return;
    const int r    = g_tileRel[tile];
    const int row0 = tile << 7;

    const int tid = threadIdx.x, wid = tid >> 5, lane = tid & 31;
    const int g = lane >> 2, tg = lane & 3;

    {   // meta: one packed record per thread (coalesced LDG.128)
        const int4 e = g_edge[row0 + tid];
        s_dst[tid]  = e.y;
        s_norm[tid] = __int_as_float(e.z);
    }

    // Stage W image: 2048 u32 = 512 x 16B chunks (restrided 64 -> 72).
    {
        const uint32_t* wg = g_WH + (size_t)r * WH_ROW;
        const uint32_t wsm = smem_u32(Wh);
#pragma unroll
        for (int j = 0; j < 4; j++) {
            const int idx = j * 128 + tid;
            const int kp = idx >> 4, cg = idx & 15;
            cp16(wsm + (kp * SWH + cg * 4) * 4, wg + (kp << 6) + cg * 4);
        }
    }
    // Stage A: gather 128 h-rows (32 u32 each), 8 threads/row x 16B.
    {
        const int arow = tid >> 3, c = tid & 7;
        const uint32_t asm_base = smem_u32(As);
#pragma unroll
        for (int p = 0; p < 8; p++) {
            const int row = p * 16 + arow;
            const int s = ((const int*)g_edge)[(size_t)(row0 + row) * 4];  // .x
            cp16(asm_base + (row * SAH + c * 4) * 4,
                 g_hH + ((size_t)s << 5) + c * 4);
        }
    }
    CP_COMMIT();
    CP_WAIT0();
    __syncthreads();

    // Mainloop: warp tile 32 x 64, K = 4 steps of 16. B loaded per-nt.
    float acc[2][8][4];
#pragma unroll
    for (int mt = 0; mt < 2; mt++)
#pragma unroll
        for (int nt = 0; nt < 8; nt++)
#pragma unroll
            for (int q = 0; q < 4; q++) acc[mt][nt][q] = 0.0f;

    const int wrow = wid * 32;
#pragma unroll
    for (int ks = 0; ks < 4; ks++) {
        uint32_t a[2][4];
#pragma unroll
        for (int mt = 0; mt < 2; mt++) {
            const int lr = wrow + mt * 16 + g;
            const uint2 p0 = *(const uint2*)&As[lr * SAH + ks * 8 + tg * 2];
            const uint2 p1 = *(const uint2*)&As[(lr + 8) * SAH + ks * 8 + tg * 2];
            a[mt][0] = p0.x; a[mt][1] = p1.x; a[mt][2] = p0.y; a[mt][3] = p1.y;
        }
        const int kA = (ks * 8 + tg) * SWH;
        const int kB = kA + 4 * SWH;
#pragma unroll
        for (int nt = 0; nt < 8; nt++) {
            const uint32_t b0 = Wh[kA + nt * 8 + g];
            const uint32_t b1 = Wh[kB + nt * 8 + g];
            mma_f16(acc[0][nt], a[0], b0, b1);
            mma_f16(acc[1][nt], a[1], b0, b1);
        }
    }

    // Epilogue: norm-scale into E (conflict-free STS.64), coalesced red.v4.
    __syncthreads();
#pragma unroll
    for (int mt = 0; mt < 2; mt++) {
        const int lr0 = wrow + mt * 16 + g, lr1 = lr0 + 8;
        const float n0 = s_norm[lr0], n1 = s_norm[lr1];
#pragma unroll
        for (int nt = 0; nt < 8; nt++) {
            const int oc = nt * 8 + 2 * tg;
            *(float2*)&E[lr0 * ESTR + oc] =
                make_float2(acc[mt][nt][0] * n0, acc[mt][nt][1] * n0);
            *(float2*)&E[lr1 * ESTR + oc] =
                make_float2(acc[mt][nt][2] * n1, acc[mt][nt][3] * n1);
        }
    }
    __syncthreads();

    const int erow = tid >> 4, q4 = (tid & 15) * 4;
#pragma unroll
    for (int p = 0; p < 16; p++) {
        const int row = p * 8 + erow;
        const float4 v = *(const float4*)&E[row * ESTR + q4];
        float* o = out + (size_t)s_dst[row] * DD + q4;
        asm volatile("red.global.add.v4.f32 [%0], {%1, %2, %3, %4};"
                     :: "l"(o), "f"(v.x), "f"(v.y), "f"(v.z), "f"(v.w)
                     : "memory");
    }
}

// ---------------------------------------------------------------------------
extern "C" void kernel_launch(void* const* d_in, const int* in_sizes, int n_in,
                              void* d_out, int out_size) {
    const float* h    = (const float*)d_in[0];
    const float* W    = (const float*)d_in[1];
    const int*   src  = (const int*)d_in[2];
    const int*   dst  = (const int*)d_in[3];
    const int*   rel  = (const int*)d_in[4];
    const float* norm = (const float*)d_in[5];
    float*       out  = (float*)d_out;

    const int n_edges = in_sizes[2];   // 1600000

    void* p_cnt;
    cudaGetSymbolAddress(&p_cnt, g_binCount);
    cudaMemsetAsync(out,   0, (size_t)out_size * sizeof(float), 0);
    cudaMemsetAsync(p_cnt, 0, sizeof(int) * NR, 0);

    k_convert_hist<<<(NN * 32 + 255) / 256, 256>>>(h, W, rel, n_edges);
    k_prefix<<<1, 32>>>();
    k_scatter<<<(n_edges + 511) / 512, 256>>>(src, dst, rel, norm, n_edges);

    const int smem_bytes = 9472 * 4;   // 37.9 KB
    static bool attr_set = false;
    if (!attr_set) {
        cudaFuncSetAttribute(rgcn_fused,
                             cudaFuncAttributeMaxDynamicSharedMemorySize,
                             smem_bytes);
        attr_set = true;
    }
    const int max_tiles = n_edges / TILE + NR + 1;
    rgcn_fused<<<max_tiles, 128, smem_bytes>>>(out);
}

// round 16
// speedup vs baseline: 1.1325x; 1.1325x over previous
#include <cuda_runtime.h>
#include <cuda_fp16.h>
#include <cstdint>

#define NN 50000
#define NR 32
#define DD 64
#define NE_MAX 1600000
#define TILE 128
#define PADMAX (NR * TILE)
#define SAH 40    // As stride (u32): fp16 kpair LDS.64 frags conflict-free (8g+2tg)
#define SWH 72    // Wh stride (u32): scalar B LDS conflict-free (8tg+g)
#define WH_ROW 2048   // dense global W image per relation (32 kp x 64 n, u32)
#define ESTR 72   // epilogue stride

// Packed relation-sorted edges: (src, dst, norm_bits, 0)
__device__ int4     g_edge[NE_MAX + PADMAX];
__device__ int      g_binCount[NR];
__device__ int      g_cursor[NR];
__device__ int      g_tileRel[NE_MAX / TILE + NR + 2];
__device__ int      g_numTiles;
// Precomputed fp16 operands (rounded once, fragment-ready layouts)
__device__ uint32_t g_hH[(size_t)NN * 32];
__device__ uint32_t g_WH[(size_t)NR * WH_ROW];

__device__ __forceinline__ uint32_t packh2(float lo, float hi) {
    __half2 h2 = __floats2half2_rn(lo, hi);
    return *(uint32_t*)&h2;
}
__device__ __forceinline__ void mma_f16(float* c, const uint32_t* a, const uint32_t* b) {
    asm volatile(
        "mma.sync.aligned.m16n8k16.row.col.f32.f16.f16.f32 "
        "{%0,%1,%2,%3}, {%4,%5,%6,%7}, {%8,%9}, {%0,%1,%2,%3};"
        : "+f"(c[0]), "+f"(c[1]), "+f"(c[2]), "+f"(c[3])
        : "r"(a[0]), "r"(a[1]), "r"(a[2]), "r"(a[3]), "r"(b[0]), "r"(b[1]));
}
__device__ __forceinline__ uint32_t smem_u32(const void* p) {
    uint32_t a;
    asm("{ .reg .u64 t; cvta.to.shared.u64 t, %1; cvt.u32.u64 %0, t; }" : "=r"(a) : "l"(p));
    return a;
}
__device__ __forceinline__ void cp16(uint32_t saddr, const void* gaddr) {
    asm volatile("cp.async.ca.shared.global [%0], [%1], 16;"
                 :: "r"(saddr), "l"(gaddr) : "memory");
}
#define CP_COMMIT() asm volatile("cp.async.commit_group;" ::: "memory")
#define CP_WAIT0()  asm volatile("cp.async.wait_group 0;" ::: "memory")

// ---------------------------------------------------------------------------
// Preamble A: fp16 fragment-layout conversion + relation histogram.
// ---------------------------------------------------------------------------
__global__ void __launch_bounds__(256) k_convert_hist(const float* __restrict__ h,
                                                      const float* __restrict__ W,
                                                      const int* __restrict__ rel,
                                                      int n_edges) {
    __shared__ int sh[NR];
    if (threadIdx.x < NR) sh[threadIdx.x] = 0;
    __syncthreads();

    const int i = blockIdx.x * 256 + threadIdx.x;
    if (i < NN * 32) {
        const int n = i >> 5, kp = i & 31;
        const int slot = (kp >> 3) * 8 + (kp & 3) * 2 + ((kp >> 2) & 1);
        g_hH[(n << 5) + slot] = packh2(__ldg(h + n * DD + 2 * kp),
                                       __ldg(h + n * DD + 2 * kp + 1));
    }
    if (i < NR * 32 * DD) {
        const int r = i >> 11, kp = (i >> 6) & 31, n = i & 63;
        const float* wp = W + (size_t)r * DD * DD + 2 * kp * DD + n;
        g_WH[(size_t)r * WH_ROW + (kp << 6) + n] = packh2(__ldg(wp), __ldg(wp + DD));
    }
    if (i < n_edges) atomicAdd(&sh[__ldg(rel + i)], 1);
    __syncthreads();
    if (threadIdx.x < NR && sh[threadIdx.x] > 0)
        atomicAdd(&g_binCount[threadIdx.x], sh[threadIdx.x]);
}

// ---------------------------------------------------------------------------
// Preamble B: prefix + tile->rel map + pad zeroing, parallelized. 128 threads:
// warp 0 scans; then 4 warps x 8 relations stride-write maps and pads.
// ---------------------------------------------------------------------------
__global__ void __launch_bounds__(128) k_prefix() {
    __shared__ int s_base[NR], s_cnt[NR], s_tbase[NR], s_tiles[NR];
    const int tid = threadIdx.x, wid = tid >> 5, lane = tid & 31;

    if (wid == 0) {
        const int r = lane;
        const int cnt = g_binCount[r];
        const int tiles = (cnt + TILE - 1) / TILE;
        int t = tiles;
#pragma unroll
        for (int d = 1; d < 32; d <<= 1) {
            int v = __shfl_up_sync(0xFFFFFFFFu, t, d);
            if (r >= d) t += v;
        }
        const int tileBase = t - tiles;
        const int base = tileBase * TILE;
        g_cursor[r] = base;
        s_base[r] = base; s_cnt[r] = cnt; s_tbase[r] = tileBase; s_tiles[r] = tiles;
        if (r == 31) g_numTiles = t;
    }
    __syncthreads();

    for (int r = wid; r < NR; r += 4) {
        const int tb = s_tbase[r], nt = s_tiles[r];
        for (int i = lane; i < nt; i += 32) g_tileRel[tb + i] = r;
        const int p0 = s_base[r] + s_cnt[r], p1 = s_base[r] + nt * TILE;
        for (int i = p0 + lane; i < p1; i += 32) g_edge[i] = make_int4(0, 0, 0, 0);
    }
}

// ---------------------------------------------------------------------------
// Preamble C: scatter, 4 edges per thread (1024 per block).
// ---------------------------------------------------------------------------
__global__ void __launch_bounds__(256) k_scatter(const int* __restrict__ src,
                                                 const int* __restrict__ dst,
                                                 const int* __restrict__ rel,
                                                 const float* __restrict__ norm,
                                                 int n) {
    __shared__ int sh_cnt[NR], sh_base[NR];
    const int tid = threadIdx.x;
    if (tid < NR) sh_cnt[tid] = 0;
    __syncthreads();

    int  rr[4], rk[4];
    int4 ee[4];
    bool ok[4];
#pragma unroll
    for (int j = 0; j < 4; j++) {
        const int i = blockIdx.x * 1024 + j * 256 + tid;
        ok[j] = i < n;
        if (ok[j]) {
            rr[j] = __ldg(rel + i);
            ee[j] = make_int4(__ldg(src + i), __ldg(dst + i),
                              __float_as_int(__ldg(norm + i)), 0);
            rk[j] = atomicAdd(&sh_cnt[rr[j]], 1);
        }
    }
    __syncthreads();
    if (tid < NR && sh_cnt[tid] > 0)
        sh_base[tid] = atomicAdd(&g_cursor[tid], sh_cnt[tid]);
    __syncthreads();
#pragma unroll
    for (int j = 0; j < 4; j++)
        if (ok[j]) g_edge[sh_base[rr[j]] + rk[j]] = ee[j];
}

// ---------------------------------------------------------------------------
// Fused kernel (R14 verbatim): one 128-edge tile per block, fp16 m16n8k16.
// Smem 37.9 KB, __launch_bounds__(128,5): 96 regs, 5 blocks/SM. Measured
// 113.6us; both the 6-block (reg-squeezed) and 2-block (pipelined) variants
// regressed, so this configuration is pinned.
// ---------------------------------------------------------------------------
__global__ void __launch_bounds__(128, 5) rgcn_fused(float* __restrict__ out) {
    extern __shared__ uint32_t smem[];
    uint32_t* Wh     = smem;                  // 2304
    uint32_t* As     = smem + 32 * SWH;       // 5120
    float*    E      = (float*)smem;          // epilogue overlay 128x72
    int*      s_dst  = (int*)(smem + 9216);   // 128
    float*    s_norm = (float*)(s_dst + 128); // 128

    const int tile = blockIdx.x;
    if (tile >= g_numTiles) return;
    const int r    = g_tileRel[tile];
    const int row0 = tile << 7;

    const int tid = threadIdx.x, wid = tid >> 5, lane = tid & 31;
    const int g = lane >> 2, tg = lane & 3;

    {   // meta: one packed record per thread (coalesced LDG.128)
        const int4 e = g_edge[row0 + tid];
        s_dst[tid]  = e.y;
        s_norm[tid] = __int_as_float(e.z);
    }

    // Stage W image: 2048 u32 = 512 x 16B chunks (restrided 64 -> 72).
    {
        const uint32_t* wg = g_WH + (size_t)r * WH_ROW;
        const uint32_t wsm = smem_u32(Wh);
#pragma unroll
        for (int j = 0; j < 4; j++) {
            const int idx = j * 128 + tid;
            const int kp = idx >> 4, cg = idx & 15;
            cp16(wsm + (kp * SWH + cg * 4) * 4, wg + (kp << 6) + cg * 4);
        }
    }
    // Stage A: gather 128 h-rows (32 u32 each), 8 threads/row x 16B.
    {
        const int arow = tid >> 3, c = tid & 7;
        const uint32_t asm_base = smem_u32(As);
#pragma unroll
        for (int p = 0; p < 8; p++) {
            const int row = p * 16 + arow;
            const int s = ((const int*)g_edge)[(size_t)(row0 + row) * 4];  // .x
            cp16(asm_base + (row * SAH + c * 4) * 4,
                 g_hH + ((size_t)s << 5) + c * 4);
        }
    }
    CP_COMMIT();
    CP_WAIT0();
    __syncthreads();

    // Mainloop: warp tile 32 x 64, K = 4 steps of 16.
    float acc[2][8][4];
#pragma unroll
    for (int mt = 0; mt < 2; mt++)
#pragma unroll
        for (int nt = 0; nt < 8; nt++)
#pragma unroll
            for (int q = 0; q < 4; q++) acc[mt][nt][q] = 0.0f;

    const int wrow = wid * 32;
#pragma unroll
    for (int ks = 0; ks < 4; ks++) {
        uint32_t a[2][4];
#pragma unroll
        for (int mt = 0; mt < 2; mt++) {
            const int lr = wrow + mt * 16 + g;
            const uint2 p0 = *(const uint2*)&As[lr * SAH + ks * 8 + tg * 2];
            const uint2 p1 = *(const uint2*)&As[(lr + 8) * SAH + ks * 8 + tg * 2];
            a[mt][0] = p0.x; a[mt][1] = p1.x; a[mt][2] = p0.y; a[mt][3] = p1.y;
        }
        uint32_t b[8][2];
        const int kA = (ks * 8 + tg) * SWH;
        const int kB = kA + 4 * SWH;
#pragma unroll
        for (int nt = 0; nt < 8; nt++) {
            b[nt][0] = Wh[kA + nt * 8 + g];
            b[nt][1] = Wh[kB + nt * 8 + g];
        }
#pragma unroll
        for (int mt = 0; mt < 2; mt++)
#pragma unroll
            for (int nt = 0; nt < 8; nt++)
                mma_f16(acc[mt][nt], a[mt], b[nt]);
    }

    // Epilogue: norm-scale into E (conflict-free STS.64), coalesced red.v4.
    __syncthreads();
#pragma unroll
    for (int mt = 0; mt < 2; mt++) {
        const int lr0 = wrow + mt * 16 + g, lr1 = lr0 + 8;
        const float n0 = s_norm[lr0], n1 = s_norm[lr1];
#pragma unroll
        for (int nt = 0; nt < 8; nt++) {
            const int oc = nt * 8 + 2 * tg;
            *(float2*)&E[lr0 * ESTR + oc] =
                make_float2(acc[mt][nt][0] * n0, acc[mt][nt][1] * n0);
            *(float2*)&E[lr1 * ESTR + oc] =
                make_float2(acc[mt][nt][2] * n1, acc[mt][nt][3] * n1);
        }
    }
    __syncthreads();

    const int erow = tid >> 4, q4 = (tid & 15) * 4;
#pragma unroll
    for (int p = 0; p < 16; p++) {
        const int row = p * 8 + erow;
        const float4 v = *(const float4*)&E[row * ESTR + q4];
        float* o = out + (size_t)s_dst[row] * DD + q4;
        asm volatile("red.global.add.v4.f32 [%0], {%1, %2, %3, %4};"
                     :: "l"(o), "f"(v.x), "f"(v.y), "f"(v.z), "f"(v.w)
                     : "memory");
    }
}

// ---------------------------------------------------------------------------
extern "C" void kernel_launch(void* const* d_in, const int* in_sizes, int n_in,
                              void* d_out, int out_size) {
    const float* h    = (const float*)d_in[0];
    const float* W    = (const float*)d_in[1];
    const int*   src  = (const int*)d_in[2];
    const int*   dst  = (const int*)d_in[3];
    const int*   rel  = (const int*)d_in[4];
    const float* norm = (const float*)d_in[5];
    float*       out  = (float*)d_out;

    const int n_edges = in_sizes[2];   // 1600000

    void* p_cnt;
    cudaGetSymbolAddress(&p_cnt, g_binCount);
    cudaMemsetAsync(out,   0, (size_t)out_size * sizeof(float), 0);
    cudaMemsetAsync(p_cnt, 0, sizeof(int) * NR, 0);

    k_convert_hist<<<(NN * 32 + 255) / 256, 256>>>(h, W, rel, n_edges);
    k_prefix<<<1, 128>>>();
    k_scatter<<<(n_edges + 1023) / 1024, 256>>>(src, dst, rel, norm, n_edges);

    const int smem_bytes = 9472 * 4;   // 37.9 KB
    static bool attr_set = false;
    if (!attr_set) {
        cudaFuncSetAttribute(rgcn_fused,
                             cudaFuncAttributeMaxDynamicSharedMemorySize,
                             smem_bytes);
        attr_set = true;
    }
    const int max_tiles = n_edges / TILE + NR + 1;
    rgcn_fused<<<max_tiles, 128, smem_bytes>>>(out);
}